// round 10
// baseline (speedup 1.0000x reference)
#include <cuda_runtime.h>

// Staggered parallel transport, 8 paths, 32^4 lattice — fused kernel with
// 3-threads-per-site decomposition (lane = (site, color-row)) to cut L1tex
// wavefronts: U loads go from 9 wf/LDG (stride-36B) to 3 wf/LDG (stride-12B),
// x loads become 3-lane broadcasts (~1 wf), stores perfectly coalesced (1 wf).
//
// Layouts (row-major, metadata order):
//   d_in[0] x_re : (8, V, 3) float    d_in[1] x_im : (8, V, 3)
//   d_in[2] U_re : (4, V, 9) float    d_in[3] U_im : (4, V, 9)
//   d_out        : (2, 8, V, 3) float   (re block then im block)
// site s = ((x*32 + y)*32 + z)*32 + t
//
// Channels:
//   0: copy            1: fwd mu=0       2: fwd mu=1   3: fwd mu=2
//   4: fwd mu=3        5: bwd mu=0 (scatter)   6: bwd mu=1 (scatter)
//   7: fwd mu=0 then fwd mu=1  — first hop in SMEM (y-tiled block + halo)
//
// Block = 768 threads = 3 x (t:32, y:8) at fixed (x, z).
//   tid = yl*96 + r,  r = 3*t + a   (96 = exactly 3 warps per y-row)
// Thread (t, a) computes output color component a of every channel at site s.
//   forward hop  (U v):    needs row a    of U
//   backward hop (U^dag v): needs column a of U

#define VOL (32 * 32 * 32 * 32)

__global__ void __launch_bounds__(768, 2)
k_fused(const float* __restrict__ xr, const float* __restrict__ xi,
        const float* __restrict__ Ur, const float* __restrict__ Ui,
        float* __restrict__ out) {
    // ch7 intermediate: [y-row 0..8][t][component 0..5]  (re 0..2, im 3..5)
    __shared__ float tmp_s[9][32][6];

    int tid = threadIdx.x;
    int yl = tid / 96;            // 0..7  (y-row; 3 warps each)
    int r = tid - yl * 96;        // 0..95
    int t = r / 3;                // 0..31
    int a = r - t * 3;            // 0..2  color row

    int bid = blockIdx.x;         // 0..4095
    int y0 = (bid & 3) << 3;      // {0,8,16,24}
    int z = (bid >> 2) & 31;
    int x = bid >> 7;

    int y = y0 + yl;
    int s = (x << 15) | (y << 10) | (z << 5) | t;

    int s_px = (s & ~(31 << 15)) | (((x + 1) & 31) << 15);
    int s_py = (s & ~(31 << 10)) | (((y + 1) & 31) << 10);
    int s_pz = (s & ~(31 << 5)) | (((z + 1) & 31) << 5);
    int s_pt = (s & ~31) | ((t + 1) & 31);

    float eta1 = (x & 1) ? -1.f : 1.f;            // (-1)^x
    float eta2 = ((x ^ y) & 1) ? -1.f : 1.f;      // (-1)^(x+y)
    float eta3 = ((x ^ y ^ z) & 1) ? -1.f : 1.f;  // (-1)^(x+y+z)

    float Rr[3], Ri[3], Cr[3], Ci[3], vr[3], vi[3];
    float ore, oim;

    // ---- ch0: identity copy (perfectly coalesced, 1 wf/inst) ----
    {
        int b0 = (0 * VOL + s) * 3 + a;
        out[(0 * VOL + s) * 3 + a] = __ldg(xr + b0);
        out[((8 + 0) * VOL + s) * 3 + a] = __ldg(xi + b0);
    }

    // ================= U0 section: ch1, ch5, ch7-hop1 =================
    {
        int ub = (0 * VOL + s) * 9;
#pragma unroll
        for (int b = 0; b < 3; b++) {
            Rr[b] = __ldg(Ur + ub + a * 3 + b);   // row a
            Ri[b] = __ldg(Ui + ub + a * 3 + b);
            Cr[b] = __ldg(Ur + ub + b * 3 + a);   // column a
            Ci[b] = __ldg(Ui + ub + b * 3 + a);
        }

        // ch1: out1(s)[a] = (U0(s) x1(s+x))[a]          (eta0 = 1)
        {
            int vb = (1 * VOL + s_px) * 3;
            ore = 0.f; oim = 0.f;
#pragma unroll
            for (int b = 0; b < 3; b++) {
                float wr = __ldg(xr + vb + b), wi = __ldg(xi + vb + b);
                ore = fmaf(Rr[b], wr, ore); ore = fmaf(-Ri[b], wi, ore);
                oim = fmaf(Rr[b], wi, oim); oim = fmaf(Ri[b], wr, oim);
            }
            out[(1 * VOL + s) * 3 + a] = ore;
            out[((8 + 1) * VOL + s) * 3 + a] = oim;
        }

        // ch5 (scatter): out5(s+x)[a] = (U0^dag(s) x5(s))[a]
        {
            int vb = (5 * VOL + s) * 3;
            ore = 0.f; oim = 0.f;
#pragma unroll
            for (int b = 0; b < 3; b++) {
                float wr = __ldg(xr + vb + b), wi = __ldg(xi + vb + b);
                // conj(C[b]) * w
                ore = fmaf(Cr[b], wr, ore); ore = fmaf(Ci[b], wi, ore);
                oim = fmaf(Cr[b], wi, oim); oim = fmaf(-Ci[b], wr, oim);
            }
            out[(5 * VOL + s_px) * 3 + a] = ore;
            out[((8 + 5) * VOL + s_px) * 3 + a] = oim;
        }

        // ch7 hop 1 -> smem: tmp(s)[a] = (U0(s) x7(s+x))[a]
        {
            int vb = (7 * VOL + s_px) * 3;
            ore = 0.f; oim = 0.f;
#pragma unroll
            for (int b = 0; b < 3; b++) {
                float wr = __ldg(xr + vb + b), wi = __ldg(xi + vb + b);
                ore = fmaf(Rr[b], wr, ore); ore = fmaf(-Ri[b], wi, ore);
                oim = fmaf(Rr[b], wi, oim); oim = fmaf(Ri[b], wr, oim);
            }
            tmp_s[yl][t][a] = ore;
            tmp_s[yl][t][3 + a] = oim;
        }

        // halo row y0+8 (y-row 0 threads = 3 warps; warp-uniform branch)
        if (yl == 0) {
            int yh = (y0 + 8) & 31;
            int sh = (x << 15) | (yh << 10) | (z << 5) | t;
            int sh_px = (sh & ~(31 << 15)) | (((x + 1) & 31) << 15);
            int uhb = (0 * VOL + sh) * 9;
            int vb = (7 * VOL + sh_px) * 3;
            ore = 0.f; oim = 0.f;
#pragma unroll
            for (int b = 0; b < 3; b++) {
                float ur = __ldg(Ur + uhb + a * 3 + b);
                float ui = __ldg(Ui + uhb + a * 3 + b);
                float wr = __ldg(xr + vb + b), wi = __ldg(xi + vb + b);
                ore = fmaf(ur, wr, ore); ore = fmaf(-ui, wi, ore);
                oim = fmaf(ur, wi, oim); oim = fmaf(ui, wr, oim);
            }
            tmp_s[8][t][a] = ore;
            tmp_s[8][t][3 + a] = oim;
        }
    }

    // ================= U2 section: ch3 =================
    {
        int ub = (2 * VOL + s) * 9;
        int vb = (3 * VOL + s_pz) * 3;
        ore = 0.f; oim = 0.f;
#pragma unroll
        for (int b = 0; b < 3; b++) {
            float ur = __ldg(Ur + ub + a * 3 + b);
            float ui = __ldg(Ui + ub + a * 3 + b);
            float wr = __ldg(xr + vb + b), wi = __ldg(xi + vb + b);
            ore = fmaf(ur, wr, ore); ore = fmaf(-ui, wi, ore);
            oim = fmaf(ur, wi, oim); oim = fmaf(ui, wr, oim);
        }
        out[(3 * VOL + s) * 3 + a] = eta2 * ore;
        out[((8 + 3) * VOL + s) * 3 + a] = eta2 * oim;
    }

    // ================= U3 section: ch4 =================
    {
        int ub = (3 * VOL + s) * 9;
        int vb = (4 * VOL + s_pt) * 3;
        ore = 0.f; oim = 0.f;
#pragma unroll
        for (int b = 0; b < 3; b++) {
            float ur = __ldg(Ur + ub + a * 3 + b);
            float ui = __ldg(Ui + ub + a * 3 + b);
            float wr = __ldg(xr + vb + b), wi = __ldg(xi + vb + b);
            ore = fmaf(ur, wr, ore); ore = fmaf(-ui, wi, ore);
            oim = fmaf(ur, wi, oim); oim = fmaf(ui, wr, oim);
        }
        out[(4 * VOL + s) * 3 + a] = eta3 * ore;
        out[((8 + 4) * VOL + s) * 3 + a] = eta3 * oim;
    }

    __syncthreads();   // tmp_s complete block-wide

    // ================= U1 section: ch2, ch6, ch7-final =================
    {
        int ub = (1 * VOL + s) * 9;
#pragma unroll
        for (int b = 0; b < 3; b++) {
            Rr[b] = __ldg(Ur + ub + a * 3 + b);   // row a
            Ri[b] = __ldg(Ui + ub + a * 3 + b);
            Cr[b] = __ldg(Ur + ub + b * 3 + a);   // column a
            Ci[b] = __ldg(Ui + ub + b * 3 + a);
        }

        // ch2: out2(s)[a] = eta1 (U1(s) x2(s+y))[a]
        {
            int vb = (2 * VOL + s_py) * 3;
            ore = 0.f; oim = 0.f;
#pragma unroll
            for (int b = 0; b < 3; b++) {
                float wr = __ldg(xr + vb + b), wi = __ldg(xi + vb + b);
                ore = fmaf(Rr[b], wr, ore); ore = fmaf(-Ri[b], wi, ore);
                oim = fmaf(Rr[b], wi, oim); oim = fmaf(Ri[b], wr, oim);
            }
            out[(2 * VOL + s) * 3 + a] = eta1 * ore;
            out[((8 + 2) * VOL + s) * 3 + a] = eta1 * oim;
        }

        // ch6 (scatter): out6(s+y)[a] = eta1 (U1^dag(s) x6(s))[a]
        {
            int vb = (6 * VOL + s) * 3;
            ore = 0.f; oim = 0.f;
#pragma unroll
            for (int b = 0; b < 3; b++) {
                float wr = __ldg(xr + vb + b), wi = __ldg(xi + vb + b);
                ore = fmaf(Cr[b], wr, ore); ore = fmaf(Ci[b], wi, ore);
                oim = fmaf(Cr[b], wi, oim); oim = fmaf(-Ci[b], wr, oim);
            }
            out[(6 * VOL + s_py) * 3 + a] = eta1 * ore;
            out[((8 + 6) * VOL + s_py) * 3 + a] = eta1 * oim;
        }

        // ch7: out7(s)[a] = eta1 (U1(s) tmp(s+y))[a]   [smem, broadcast reads]
        {
#pragma unroll
            for (int b = 0; b < 3; b++) {
                vr[b] = tmp_s[yl + 1][t][b];
                vi[b] = tmp_s[yl + 1][t][3 + b];
            }
            ore = 0.f; oim = 0.f;
#pragma unroll
            for (int b = 0; b < 3; b++) {
                ore = fmaf(Rr[b], vr[b], ore); ore = fmaf(-Ri[b], vi[b], ore);
                oim = fmaf(Rr[b], vi[b], oim); oim = fmaf(Ri[b], vr[b], oim);
            }
            out[(7 * VOL + s) * 3 + a] = eta1 * ore;
            out[((8 + 7) * VOL + s) * 3 + a] = eta1 * oim;
        }
    }
}

extern "C" void kernel_launch(void* const* d_in, const int* in_sizes, int n_in,
                              void* d_out, int out_size) {
    const float* xr = (const float*)d_in[0];
    const float* xi = (const float*)d_in[1];
    const float* Ur = (const float*)d_in[2];
    const float* Ui = (const float*)d_in[3];
    float* out = (float*)d_out;

    k_fused<<<4096, 768>>>(xr, xi, Ur, Ui, out);
}

// round 12
// speedup vs baseline: 1.0741x; 1.0741x over previous
#include <cuda_runtime.h>

// Staggered parallel transport, 8 paths, 32^4 lattice — R9 structure plus
// upfront per-warp SMEM staging of U0/U1 (the 3-matvec sections) to cut
// L1tex wavefronts: 162 wf -> 18 LDG-wf + 18 conflict-free LDS per section.
//
// Layouts (row-major, metadata order):
//   d_in[0] x_re : (8, V, 3) float    d_in[1] x_im : (8, V, 3)
//   d_in[2] U_re : (4, V, 9) float    d_in[3] U_im : (4, V, 9)
//   d_out        : (2, 8, V, 3) float   (re block then im block)
// site s = ((x*32 + y)*32 + z)*32 + t
//
// Channels:
//   0: copy            1: fwd mu=0       2: fwd mu=1   3: fwd mu=2
//   4: fwd mu=3        5: bwd mu=0 (scatter)   6: bwd mu=1 (scatter)
//   7: fwd mu=0 then fwd mu=1  — first hop in SMEM (y-tiled block + halo)
//
// Block = 256 threads = (t:32, y:8) at fixed (x, z); warp <-> one t-line.
// Staging: warp's 32 sites own 288 contiguous floats of U0/U1 (re and im);
// 9 coalesced LDGs fill each; LDS readback t*9+k hits distinct banks (9⊥32).

#define VOL (32 * 32 * 32 * 32)

__device__ __forceinline__ void mv(const float* __restrict__ Ur,
                                   const float* __restrict__ Ui,
                                   const float* vr, const float* vi,
                                   float sgn, float* yr, float* yi) {
#pragma unroll
    for (int a = 0; a < 3; a++) {
        float sr = 0.f, si = 0.f;
#pragma unroll
        for (int b = 0; b < 3; b++) {
            float ur = Ur[a * 3 + b], ui = Ui[a * 3 + b];
            sr = fmaf(ur, vr[b], sr);
            sr = fmaf(-ui, vi[b], sr);
            si = fmaf(ur, vi[b], si);
            si = fmaf(ui, vr[b], si);
        }
        yr[a] = sgn * sr;
        yi[a] = sgn * si;
    }
}

__device__ __forceinline__ void mvdag(const float* __restrict__ Ur,
                                      const float* __restrict__ Ui,
                                      const float* vr, const float* vi,
                                      float sgn, float* yr, float* yi) {
#pragma unroll
    for (int a = 0; a < 3; a++) {
        float sr = 0.f, si = 0.f;
#pragma unroll
        for (int b = 0; b < 3; b++) {
            float ur = Ur[b * 3 + a], ui = Ui[b * 3 + a];  // conj-transpose
            sr = fmaf(ur, vr[b], sr);
            sr = fmaf(ui, vi[b], sr);
            si = fmaf(ur, vi[b], si);
            si = fmaf(-ui, vr[b], si);
        }
        yr[a] = sgn * sr;
        yi[a] = sgn * si;
    }
}

__device__ __forceinline__ void ldv(const float* __restrict__ xr,
                                    const float* __restrict__ xi,
                                    int ch, int s, float* vr, float* vi) {
    int b = (ch * VOL + s) * 3;
#pragma unroll
    for (int c = 0; c < 3; c++) {
        vr[c] = __ldg(xr + b + c);
        vi[c] = __ldg(xi + b + c);
    }
}

__device__ __forceinline__ void ldU(const float* __restrict__ Ur,
                                    const float* __restrict__ Ui,
                                    int mu, int s, float* ur, float* ui) {
    int b = (mu * VOL + s) * 9;
#pragma unroll
    for (int k = 0; k < 9; k++) {
        ur[k] = __ldg(Ur + b + k);
        ui[k] = __ldg(Ui + b + k);
    }
}

__device__ __forceinline__ void stv(float* __restrict__ out, int ch, int s,
                                    const float* yr, const float* yi) {
    int br = (ch * VOL + s) * 3;
    int bi = ((8 + ch) * VOL + s) * 3;
#pragma unroll
    for (int c = 0; c < 3; c++) {
        out[br + c] = yr[c];
        out[bi + c] = yi[c];
    }
}

__global__ void __launch_bounds__(256, 4)
k_fused(const float* __restrict__ xr, const float* __restrict__ xi,
        const float* __restrict__ Ur, const float* __restrict__ Ui,
        float* __restrict__ out) {
    // ch7 intermediate: [component 0..5][y-row 0..8][t]
    __shared__ float tmp_s[6][9][32];
    // per-warp staging for U0 and U1: [warp][re/im][288 floats]
    __shared__ float uA[8][2][288];
    __shared__ float uB[8][2][288];

    int tid = threadIdx.x;
    int t = tid & 31;
    int yl = tid >> 5;            // 0..7

    int bid = blockIdx.x;         // 0..4095
    int y0 = (bid & 3) << 3;      // {0,8,16,24}
    int z = (bid >> 2) & 31;
    int x = bid >> 7;

    int y = y0 + yl;
    int s = (x << 15) | (y << 10) | (z << 5) | t;
    int sline = s & ~31;          // lane-0 site of this warp's t-line

    int s_px = (s & ~(31 << 15)) | (((x + 1) & 31) << 15);
    int s_py = (s & ~(31 << 10)) | (((y + 1) & 31) << 10);
    int s_pz = (s & ~(31 << 5)) | (((z + 1) & 31) << 5);
    int s_pt = (s & ~31) | ((t + 1) & 31);

    float eta1 = (x & 1) ? -1.f : 1.f;            // (-1)^x
    float eta2 = ((x ^ y) & 1) ? -1.f : 1.f;      // (-1)^(x+y)
    float eta3 = ((x ^ y ^ z) & 1) ? -1.f : 1.f;  // (-1)^(x+y+z)

    float vr[3], vi[3], yr[3], yi[3];

    // ---- upfront coalesced staging of U0 and U1 (independent LDG streams) ----
    {
        int b0 = (0 * VOL + sline) * 9 + t;
        int b1 = (1 * VOL + sline) * 9 + t;
#pragma unroll
        for (int k = 0; k < 9; k++) {
            uA[yl][0][k * 32 + t] = __ldg(Ur + b0 + k * 32);
            uA[yl][1][k * 32 + t] = __ldg(Ui + b0 + k * 32);
            uB[yl][0][k * 32 + t] = __ldg(Ur + b1 + k * 32);
            uB[yl][1][k * 32 + t] = __ldg(Ui + b1 + k * 32);
        }
    }

    // ch0: identity copy (independent; overlaps staging latency)
    ldv(xr, xi, 0, s, vr, vi);
    stv(out, 0, s, vr, vi);

    __syncwarp();

    // ---- mu = 0 block: U0 from smem; serves ch1, ch5, ch7 first hop ----
    {
        float U0r[9], U0i[9];
#pragma unroll
        for (int k = 0; k < 9; k++) {
            U0r[k] = uA[yl][0][t * 9 + k];   // conflict-free: 9 ⟂ 32
            U0i[k] = uA[yl][1][t * 9 + k];
        }

        // ch1: out1(s) = U0(s) x1(s + x_hat)       (eta0 = 1)
        ldv(xr, xi, 1, s_px, vr, vi);
        mv(U0r, U0i, vr, vi, 1.f, yr, yi);
        stv(out, 1, s, yr, yi);

        // ch5 (scatter): out5(s + x_hat) = U0^dag(s) x5(s)
        ldv(xr, xi, 5, s, vr, vi);
        mvdag(U0r, U0i, vr, vi, 1.f, yr, yi);
        stv(out, 5, s_px, yr, yi);

        // ch7 first hop -> smem: tmp(s) = U0(s) x7(s + x_hat)
        ldv(xr, xi, 7, s_px, vr, vi);
        mv(U0r, U0i, vr, vi, 1.f, yr, yi);
#pragma unroll
        for (int c = 0; c < 3; c++) {
            tmp_s[c][yl][t] = yr[c];
            tmp_s[3 + c][yl][t] = yi[c];
        }

        // halo row y0+8 (warp 0 only; direct register loads, reuses arrays)
        if (yl == 0) {
            int yh = (y0 + 8) & 31;
            int sh = (x << 15) | (yh << 10) | (z << 5) | t;
            int sh_px = (sh & ~(31 << 15)) | (((x + 1) & 31) << 15);
            ldU(Ur, Ui, 0, sh, U0r, U0i);
            ldv(xr, xi, 7, sh_px, vr, vi);
            mv(U0r, U0i, vr, vi, 1.f, yr, yi);
#pragma unroll
            for (int c = 0; c < 3; c++) {
                tmp_s[c][8][t] = yr[c];
                tmp_s[3 + c][8][t] = yi[c];
            }
        }
    }

    // ---- mu = 2: ch3 (direct register loads, single matvec) ----
    {
        float U2r[9], U2i[9];
        ldU(Ur, Ui, 2, s, U2r, U2i);
        ldv(xr, xi, 3, s_pz, vr, vi);
        mv(U2r, U2i, vr, vi, eta2, yr, yi);
        stv(out, 3, s, yr, yi);
    }

    // ---- mu = 3: ch4 ----
    {
        float U3r[9], U3i[9];
        ldU(Ur, Ui, 3, s, U3r, U3i);
        ldv(xr, xi, 4, s_pt, vr, vi);
        mv(U3r, U3i, vr, vi, eta3, yr, yi);
        stv(out, 4, s, yr, yi);
    }

    __syncthreads();

    // ---- mu = 1 block: U1 from smem; serves ch2, ch6, ch7 second hop ----
    {
        float U1r[9], U1i[9];
#pragma unroll
        for (int k = 0; k < 9; k++) {
            U1r[k] = uB[yl][0][t * 9 + k];
            U1i[k] = uB[yl][1][t * 9 + k];
        }

        // ch2: out2(s) = eta1(s) U1(s) x2(s + y_hat)
        ldv(xr, xi, 2, s_py, vr, vi);
        mv(U1r, U1i, vr, vi, eta1, yr, yi);
        stv(out, 2, s, yr, yi);

        // ch6 (scatter): out6(s + y_hat) = eta1(s) U1^dag(s) x6(s)
        ldv(xr, xi, 6, s, vr, vi);
        mvdag(U1r, U1i, vr, vi, eta1, yr, yi);
        stv(out, 6, s_py, yr, yi);

        // ch7: out7(s) = eta1(s) U1(s) tmp(s + y_hat)   [smem]
#pragma unroll
        for (int c = 0; c < 3; c++) {
            vr[c] = tmp_s[c][yl + 1][t];
            vi[c] = tmp_s[3 + c][yl + 1][t];
        }
        mv(U1r, U1i, vr, vi, eta1, yr, yi);
        stv(out, 7, s, yr, yi);
    }
}

extern "C" void kernel_launch(void* const* d_in, const int* in_sizes, int n_in,
                              void* d_out, int out_size) {
    const float* xr = (const float*)d_in[0];
    const float* xi = (const float*)d_in[1];
    const float* Ur = (const float*)d_in[2];
    const float* Ui = (const float*)d_in[3];
    float* out = (float*)d_out;

    k_fused<<<4096, 256>>>(xr, xi, Ur, Ui, out);
}